// round 8
// baseline (speedup 1.0000x reference)
#include <cuda_runtime.h>
#include <cuda_fp16.h>
#include <stdint.h>

#define NN 100000
#define FIN 128
#define HID 32
#define G3 96
#define NE 3200000
#define NEPAD (NE + 4 * NN)

// ---- device scratch ----
__device__ float g_dinv[NN];
__device__ float g_deg[NN];
__device__ int   g_cnt[NN];
__device__ int   g_rowstart[NN];
__device__ int   g_cursor[NN];
__device__ int   g_bsum[128];
__device__ unsigned long long g_edges[NEPAD];  // packed (row:int32, norm w:f32)
__device__ __half g_U[(size_t)NN * G3];        // fp16: raw x @ Vc
__device__ float g_Vc[FIN * G3];
__device__ float g_cst[G3];
__device__ float g_Wt[3 * HID * HID];
__device__ int   g_is64;

__device__ __forceinline__ int edge_idx(const void* ei, size_t pos) {
    if (g_is64) return (int)__ldg(((const long long*)ei) + pos);
    return __ldg(((const int*)ei) + pos);
}

__device__ __forceinline__ void ffma2(unsigned long long& d,
                                      unsigned long long a,
                                      unsigned long long b) {
    asm("fma.rn.f32x2 %0, %1, %2, %0;" : "+l"(d) : "l"(a), "l"(b));
}
__device__ __forceinline__ unsigned long long packff(float x, float y) {
    unsigned long long r;
    asm("mov.b64 %0, {%1, %2};" : "=l"(r) : "f"(x), "f"(y));
    return r;
}

// ---------------------------------------------------------------------------
__global__ void detect_kernel(const int* __restrict__ ei_words) {
    __shared__ int nz;
    if (threadIdx.x == 0) nz = 0;
    __syncthreads();
    for (int i = threadIdx.x; i < 4096; i += blockDim.x)
        if ((i & 1) && ei_words[i] != 0) atomicOr(&nz, 1);
    __syncthreads();
    if (threadIdx.x == 0) g_is64 = (nz == 0) ? 1 : 0;
}

// ---------------------------------------------------------------------------
__global__ void prep_kernel(
    const float* Wc0, const float* bc0, const float* Wl0, const float* bl0,
    const float* Wc1, const float* bc1, const float* Wl1, const float* bl1,
    const float* Wc2, const float* bc2, const float* Wl2, const float* bl2)
{
    const float* Wc[3] = {Wc0, Wc1, Wc2};
    const float* bc[3] = {bc0, bc1, bc2};
    const float* Wl[3] = {Wl0, Wl1, Wl2};
    const float* bl[3] = {bl0, bl1, bl2};
    int t = threadIdx.x;            // 128 threads
    int k = t;
    for (int g = 0; g < 3; g++) {
        const float* wc_row = Wc[g] + (size_t)k * HID;
        for (int j = 0; j < HID; j++) {
            const float* wl_row = Wl[g] + (size_t)j * 2 * HID;
            float s = 0.f;
            #pragma unroll
            for (int tt = 0; tt < HID; tt++) s += wc_row[tt] * wl_row[tt];
            g_Vc[k * G3 + g * HID + j] = s;
        }
    }
    if (t < G3) {
        int g = t / HID, j = t % HID;
        const float* wl_row = Wl[g] + (size_t)j * 2 * HID;
        float s = bl[g][j];
        #pragma unroll
        for (int tt = 0; tt < HID; tt++) s += bc[g][tt] * wl_row[tt];
        g_cst[t] = s;
        for (int k2 = 0; k2 < HID; k2++)
            g_Wt[g * HID * HID + k2 * HID + j] = wl_row[HID + k2];
    }
}

// ---------------------------------------------------------------------------
__global__ void init_kernel() {
    int i = blockIdx.x * blockDim.x + threadIdx.x;
    if (i < NN) { g_deg[i] = 1.0f; g_cnt[i] = 0; }
}

__global__ void count_kernel(const void* __restrict__ ei,
                             const float* __restrict__ ew) {
    int e = blockIdx.x * blockDim.x + threadIdx.x;
    if (e < NE) {
        int c = edge_idx(ei, (size_t)NE + e);
        atomicAdd(&g_cnt[c], 1);
        atomicAdd(&g_deg[c], __ldg(&ew[e]));
    }
}

// ---------------------------------------------------------------------------
// exclusive scan over PADDED counts ((cnt+3)&~3)
// ---------------------------------------------------------------------------
__global__ void __launch_bounds__(1024) scanA_kernel() {
    __shared__ int wsum[32];
    int tid = threadIdx.x, lane = tid & 31, wid = tid >> 5;
    int i = blockIdx.x * 1024 + tid;
    int v = (i < NN) ? ((g_cnt[i] + 3) & ~3) : 0;
    int s = v;
    #pragma unroll
    for (int off = 1; off < 32; off <<= 1) {
        int t = __shfl_up_sync(0xffffffffu, s, off);
        if (lane >= off) s += t;
    }
    if (lane == 31) wsum[wid] = s;
    __syncthreads();
    if (wid == 0) {
        int t = wsum[lane];
        #pragma unroll
        for (int off = 1; off < 32; off <<= 1) {
            int u = __shfl_up_sync(0xffffffffu, t, off);
            if (lane >= off) t += u;
        }
        wsum[lane] = t;
    }
    __syncthreads();
    int woff = (wid > 0) ? wsum[wid - 1] : 0;
    if (i < NN) g_rowstart[i] = s - v + woff;
    if (tid == 1023) g_bsum[blockIdx.x] = s + woff;
}

__global__ void scanB_kernel(int nblk) {
    __shared__ int tmp[128];
    int t = threadIdx.x;
    tmp[t] = (t < nblk) ? g_bsum[t] : 0;
    __syncthreads();
    if (t == 0) {
        int acc = 0;
        for (int i = 0; i < nblk; i++) { int v = tmp[i]; tmp[i] = acc; acc += v; }
    }
    __syncthreads();
    if (t < nblk) g_bsum[t] = tmp[t];
}

__global__ void __launch_bounds__(1024) scanC_kernel() {
    int i = blockIdx.x * 1024 + threadIdx.x;
    if (i < NN) {
        int rs = g_rowstart[i] + g_bsum[blockIdx.x];
        g_rowstart[i] = rs;
        g_cursor[i]   = rs;
        g_dinv[i]     = rsqrtf(g_deg[i]);
    }
}

// ---------------------------------------------------------------------------
__global__ void pad_kernel() {
    int i = blockIdx.x * blockDim.x + threadIdx.x;
    if (i >= NN) return;
    int cnt  = g_cnt[i];
    int cntp = (cnt + 3) & ~3;
    int rs   = g_rowstart[i];
    for (int k = cnt; k < cntp; k++) g_edges[rs + k] = 0ull;
}

// ---------------------------------------------------------------------------
// scatter (row, dinv[r]*w*dinv[c]) into CSR buckets
// ---------------------------------------------------------------------------
__global__ void scatter_kernel(const void* __restrict__ ei,
                               const float* __restrict__ ew) {
    int e = blockIdx.x * blockDim.x + threadIdx.x;
    if (e >= NE) return;
    int   r = edge_idx(ei, e);
    int   c = edge_idx(ei, (size_t)NE + e);
    float nw = g_dinv[r] * __ldg(&ew[e]) * g_dinv[c];
    int pos = atomicAdd(&g_cursor[c], 1);
    g_edges[pos] = (unsigned long long)(unsigned)r |
                   ((unsigned long long)__float_as_uint(nw) << 32);
}

// ---------------------------------------------------------------------------
// U = x @ Vc (raw, no dinv), f32x2 dual-FMA, fp16 output. Launch index 3 -> profiled.
// ---------------------------------------------------------------------------
__global__ void __launch_bounds__(256) gemm_u_kernel(const float* __restrict__ x) {
    __shared__ float xs[32][66];
    __shared__ float vs[32][96];
    int tid = threadIdx.x;
    int rg = tid >> 5, cj = tid & 31;
    int m0 = blockIdx.x * 64;

    unsigned long long acc[4][3];
    #pragma unroll
    for (int p = 0; p < 4; p++)
        #pragma unroll
        for (int t = 0; t < 3; t++) acc[p][t] = 0ull;

    for (int kb = 0; kb < FIN; kb += 32) {
        #pragma unroll
        for (int i = 0; i < 2; i++) {
            int s = tid + i * 256;
            int nd = s >> 3, k4 = s & 7;
            int gn = m0 + nd; if (gn >= NN) gn = NN - 1;
            float4 v = *(const float4*)&x[(size_t)gn * FIN + kb + k4 * 4];
            xs[k4 * 4 + 0][nd] = v.x;
            xs[k4 * 4 + 1][nd] = v.y;
            xs[k4 * 4 + 2][nd] = v.z;
            xs[k4 * 4 + 3][nd] = v.w;
        }
        #pragma unroll
        for (int i = 0; i < 12; i++) {
            int idx = tid + i * 256;
            int kk = idx / 96, j = idx - kk * 96;
            vs[kk][j] = g_Vc[(kb + kk) * G3 + j];
        }
        __syncthreads();
        #pragma unroll
        for (int kk = 0; kk < 32; kk++) {
            unsigned long long xp[4];
            #pragma unroll
            for (int p = 0; p < 4; p++)
                xp[p] = *(const unsigned long long*)&xs[kk][rg * 8 + p * 2];
            float b0 = vs[kk][cj], b1 = vs[kk][cj + 32], b2 = vs[kk][cj + 64];
            unsigned long long bb0 = packff(b0, b0);
            unsigned long long bb1 = packff(b1, b1);
            unsigned long long bb2 = packff(b2, b2);
            #pragma unroll
            for (int p = 0; p < 4; p++) {
                ffma2(acc[p][0], xp[p], bb0);
                ffma2(acc[p][1], xp[p], bb1);
                ffma2(acc[p][2], xp[p], bb2);
            }
        }
        __syncthreads();
    }
    #pragma unroll
    for (int p = 0; p < 4; p++) {
        int n0 = m0 + rg * 8 + p * 2;
        if (n0 >= NN) continue;
        bool ok1 = (n0 + 1 < NN);
        #pragma unroll
        for (int t = 0; t < 3; t++) {
            union { unsigned long long u; float2 f; } cv; cv.u = acc[p][t];
            g_U[(size_t)n0 * G3 + cj + t * 32] = __float2half(cv.f.x);
            if (ok1) g_U[(size_t)(n0 + 1) * G3 + cj + t * 32] = __float2half(cv.f.y);
        }
    }
}

// ---------------------------------------------------------------------------
// 4-edge gather body (12 independent fp16 loads in flight)
// ---------------------------------------------------------------------------
#define EDGE4(T)                                                               \
    {                                                                          \
        unsigned long long p0 = __shfl_sync(0xffffffffu, pk, (T));             \
        unsigned long long p1 = __shfl_sync(0xffffffffu, pk, (T) + 1);         \
        unsigned long long p2 = __shfl_sync(0xffffffffu, pk, (T) + 2);         \
        unsigned long long p3 = __shfl_sync(0xffffffffu, pk, (T) + 3);         \
        const __half* u0 = g_U + (size_t)(unsigned)p0 * G3;                    \
        const __half* u1 = g_U + (size_t)(unsigned)p1 * G3;                    \
        const __half* u2 = g_U + (size_t)(unsigned)p2 * G3;                    \
        const __half* u3 = g_U + (size_t)(unsigned)p3 * G3;                    \
        __half h00 = __ldg(u0 + lane), h01 = __ldg(u0 + lane + 32), h02 = __ldg(u0 + lane + 64); \
        __half h10 = __ldg(u1 + lane), h11 = __ldg(u1 + lane + 32), h12 = __ldg(u1 + lane + 64); \
        __half h20 = __ldg(u2 + lane), h21 = __ldg(u2 + lane + 32), h22 = __ldg(u2 + lane + 64); \
        __half h30 = __ldg(u3 + lane), h31 = __ldg(u3 + lane + 32), h32 = __ldg(u3 + lane + 64); \
        float w0 = __uint_as_float((unsigned)(p0 >> 32));                      \
        float w1 = __uint_as_float((unsigned)(p1 >> 32));                      \
        float w2 = __uint_as_float((unsigned)(p2 >> 32));                      \
        float w3 = __uint_as_float((unsigned)(p3 >> 32));                      \
        a0 = fmaf(w0, __half2float(h00), a0); a1 = fmaf(w0, __half2float(h01), a1); a2 = fmaf(w0, __half2float(h02), a2); \
        a0 = fmaf(w1, __half2float(h10), a0); a1 = fmaf(w1, __half2float(h11), a1); a2 = fmaf(w1, __half2float(h12), a2); \
        a0 = fmaf(w2, __half2float(h20), a0); a1 = fmaf(w2, __half2float(h21), a1); a2 = fmaf(w2, __half2float(h22), a2); \
        a0 = fmaf(w3, __half2float(h30), a0); a1 = fmaf(w3, __half2float(h31), a1); a2 = fmaf(w3, __half2float(h32), a2); \
    }

// ---------------------------------------------------------------------------
// fused gather + gates + head. PURE FUNCTION of precomputed arrays -> idempotent.
// ---------------------------------------------------------------------------
__global__ void __launch_bounds__(256) gather_gates_kernel(
    const float* __restrict__ hprev,
    const float* __restrict__ whead,
    const float* __restrict__ bhead,
    float* __restrict__ out)
{
    __shared__ float Ws[3 * HID * HID];
    __shared__ float csts[G3];
    int tid = threadIdx.x;
    for (int i = tid; i < 3 * HID * HID; i += 256) Ws[i] = g_Wt[i];
    if (tid < G3) csts[tid] = g_cst[tid];
    __syncthreads();

    int warp = tid >> 5, lane = tid & 31;
    int n = blockIdx.x * 8 + warp;       // grid = 12500 -> exactly N nodes

    float dc = __ldg(&g_dinv[n]);
    float sl = dc * dc;                  // self-loop norm
    const __half* un = g_U + (size_t)n * G3;
    float a0 = sl * __half2float(__ldg(un + lane));
    float a1 = sl * __half2float(__ldg(un + lane + 32));
    float a2 = sl * __half2float(__ldg(un + lane + 64));

    int start = __ldg(&g_rowstart[n]);
    int cntp  = (__ldg(&g_cnt[n]) + 3) & ~3;
    const unsigned long long* el = g_edges + start;

    for (int b = 0; b < cntp; b += 32) {
        int m = min(32, cntp - b);       // multiple of 4
        unsigned long long pk = (lane < m) ? __ldg(&el[b + lane]) : 0ull;
        if (m == 32) {
            #pragma unroll
            for (int t = 0; t < 32; t += 4) EDGE4(t)
        } else {
            for (int t = 0; t < m; t += 4) EDGE4(t)
        }
    }

    // gates
    float h  = hprev[(size_t)n * HID + lane];
    float zp = a0 + csts[lane];
    float rp = a1 + csts[lane + 32];
    float hp = a2 + csts[lane + 64];

    const float* Wz = Ws;
    const float* Wr = Ws + HID * HID;
    const float* Wh = Ws + 2 * HID * HID;
    #pragma unroll
    for (int k = 0; k < HID; k++) {
        float hk = __shfl_sync(0xffffffffu, h, k);
        zp += hk * Wz[k * HID + lane];
        rp += hk * Wr[k * HID + lane];
    }
    float Z = 1.f / (1.f + __expf(-zp));
    float R = 1.f / (1.f + __expf(-rp));
    float hr = h * R;
    #pragma unroll
    for (int k = 0; k < HID; k++) {
        float hk = __shfl_sync(0xffffffffu, hr, k);
        hp += hk * Wh[k * HID + lane];
    }
    float Ht = tanhf(hp);
    float Hn = Z * h + (1.f - Z) * Ht;

    out[(size_t)NN + (size_t)n * HID + lane] = Hn;

    float yv = fmaxf(Hn, 0.f) * __ldg(&whead[lane]);
    #pragma unroll
    for (int off = 16; off > 0; off >>= 1)
        yv += __shfl_down_sync(0xffffffffu, yv, off);
    if (lane == 0) out[n] = yv + __ldg(bhead);
}

// ---------------------------------------------------------------------------
extern "C" void kernel_launch(void* const* d_in, const int* in_sizes, int n_in,
                              void* d_out, int out_size) {
    const float* x     = (const float*)d_in[0];
    const void*  ei    = d_in[1];
    const float* ew    = (const float*)d_in[2];
    const float* hprev = (const float*)d_in[3];
    const float* Wc[3], *bc[3], *Wl[3], *bl[3];
    for (int g = 0; g < 3; g++) {
        Wc[g] = (const float*)d_in[4 + g * 4];
        bc[g] = (const float*)d_in[5 + g * 4];
        Wl[g] = (const float*)d_in[6 + g * 4];
        bl[g] = (const float*)d_in[7 + g * 4];
    }
    const float* whead = (const float*)d_in[16];
    const float* bhead = (const float*)d_in[17];
    float* out = (float*)d_out;

    const int nscan = (NN + 1023) / 1024;   // 98

    // launch index 3 = gemm_u_kernel -> profiled by ncu
    detect_kernel<<<1, 256>>>((const int*)ei);                     // 0
    prep_kernel<<<1, 128>>>(Wc[0], bc[0], Wl[0], bl[0],            // 1
                            Wc[1], bc[1], Wl[1], bl[1],
                            Wc[2], bc[2], Wl[2], bl[2]);
    init_kernel<<<(NN + 255) / 256, 256>>>();                      // 2
    gemm_u_kernel<<<(NN + 63) / 64, 256>>>(x);                     // 3  <- profiled
    count_kernel<<<(NE + 255) / 256, 256>>>(ei, ew);               // 4
    scanA_kernel<<<nscan, 1024>>>();                               // 5
    scanB_kernel<<<1, 128>>>(nscan);                               // 6
    scanC_kernel<<<nscan, 1024>>>();                               // 7
    pad_kernel<<<(NN + 255) / 256, 256>>>();                       // 8
    scatter_kernel<<<(NE + 255) / 256, 256>>>(ei, ew);             // 9
    gather_gates_kernel<<<NN / 8, 256>>>(hprev, whead, bhead, out);// 10
    gather_gates_kernel<<<NN / 8, 256>>>(hprev, whead, bhead, out);// 11 (idempotent duplicate: dur delta == gather cost)
}

// round 9
// speedup vs baseline: 2.2445x; 2.2445x over previous
#include <cuda_runtime.h>
#include <cuda_fp16.h>
#include <stdint.h>

#define NN 100000
#define FIN 128
#define HID 32
#define G3 96
#define NE 3200000
#define NEPAD (NE + 4 * NN)

// ---- device scratch ----
__device__ float g_dinv[NN];
__device__ float g_deg[NN];
__device__ int   g_cnt[NN];
__device__ int   g_rowstart[NN];
__device__ int   g_cursor[NN];
__device__ int   g_bsum[128];
__device__ unsigned long long g_edges[NEPAD];  // packed (row:int32, norm w:f32)
__device__ __half g_U[(size_t)NN * G3];        // fp16: raw x @ Vc
__device__ float g_Vc[FIN * G3];
__device__ float g_cst[G3];
__device__ float g_Wt[3 * HID * HID];
__device__ int   g_is64;

__device__ __forceinline__ int edge_idx(const void* ei, size_t pos) {
    if (g_is64) return (int)__ldg(((const long long*)ei) + pos);
    return __ldg(((const int*)ei) + pos);
}

__device__ __forceinline__ void ffma2(unsigned long long& d,
                                      unsigned long long a,
                                      unsigned long long b) {
    asm("fma.rn.f32x2 %0, %1, %2, %0;" : "+l"(d) : "l"(a), "l"(b));
}
__device__ __forceinline__ unsigned long long packff(float x, float y) {
    unsigned long long r;
    asm("mov.b64 %0, {%1, %2};" : "=l"(r) : "f"(x), "f"(y));
    return r;
}

// ---------------------------------------------------------------------------
__global__ void detect_kernel(const int* __restrict__ ei_words) {
    __shared__ int nz;
    if (threadIdx.x == 0) nz = 0;
    __syncthreads();
    for (int i = threadIdx.x; i < 4096; i += blockDim.x)
        if ((i & 1) && ei_words[i] != 0) atomicOr(&nz, 1);
    __syncthreads();
    if (threadIdx.x == 0) g_is64 = (nz == 0) ? 1 : 0;
}

// ---------------------------------------------------------------------------
// parallel weight fold: grid 48 x 256. One 32-dot per thread.
//   idx in [0, 12288): Vc[k][g*32+j] = dot(Wc_g[k][:], Wl_g[j][0:32])
//   idx in [12288, 12288+96): cst
//   idx in [12384, 12384+3072): Wt
// ---------------------------------------------------------------------------
__global__ void __launch_bounds__(256) prep_kernel(
    const float* Wc0, const float* bc0, const float* Wl0, const float* bl0,
    const float* Wc1, const float* bc1, const float* Wl1, const float* bl1,
    const float* Wc2, const float* bc2, const float* Wl2, const float* bl2)
{
    const float* Wc[3] = {Wc0, Wc1, Wc2};
    const float* bc[3] = {bc0, bc1, bc2};
    const float* Wl[3] = {Wl0, Wl1, Wl2};
    const float* bl[3] = {bl0, bl1, bl2};
    int idx = blockIdx.x * 256 + threadIdx.x;

    if (idx < FIN * G3) {                      // 12288 dots
        int k  = idx / G3;
        int gj = idx - k * G3;
        int g  = gj >> 5, j = gj & 31;
        const float* wc_row = Wc[g] + (size_t)k * HID;
        const float* wl_row = Wl[g] + (size_t)j * 2 * HID;
        float s = 0.f;
        #pragma unroll
        for (int tt = 0; tt < HID; tt++) s += wc_row[tt] * wl_row[tt];
        g_Vc[k * G3 + gj] = s;
        return;
    }
    idx -= FIN * G3;
    if (idx < G3) {                            // bias fold
        int g = idx >> 5, j = idx & 31;
        const float* wl_row = Wl[g] + (size_t)j * 2 * HID;
        float s = bl[g][j];
        #pragma unroll
        for (int tt = 0; tt < HID; tt++) s += bc[g][tt] * wl_row[tt];
        g_cst[idx] = s;
        return;
    }
    idx -= G3;
    if (idx < 3 * HID * HID) {                 // Wt transpose: [g][k][j] = Wl_g[j][32+k]
        int g = idx / (HID * HID);
        int r = idx - g * HID * HID;
        int k = r >> 5, j = r & 31;
        g_Wt[idx] = Wl[g][(size_t)j * 2 * HID + HID + k];
    }
}

// ---------------------------------------------------------------------------
__global__ void init_kernel() {
    int i = blockIdx.x * blockDim.x + threadIdx.x;
    if (i < NN) { g_deg[i] = 1.0f; g_cnt[i] = 0; }
}

__global__ void count_kernel(const void* __restrict__ ei,
                             const float* __restrict__ ew) {
    int e = blockIdx.x * blockDim.x + threadIdx.x;
    if (e < NE) {
        int c = edge_idx(ei, (size_t)NE + e);
        atomicAdd(&g_cnt[c], 1);
        atomicAdd(&g_deg[c], __ldg(&ew[e]));
    }
}

// ---------------------------------------------------------------------------
// exclusive scan over PADDED counts ((cnt+3)&~3)
// ---------------------------------------------------------------------------
__global__ void __launch_bounds__(1024) scanA_kernel() {
    __shared__ int wsum[32];
    int tid = threadIdx.x, lane = tid & 31, wid = tid >> 5;
    int i = blockIdx.x * 1024 + tid;
    int v = (i < NN) ? ((g_cnt[i] + 3) & ~3) : 0;
    int s = v;
    #pragma unroll
    for (int off = 1; off < 32; off <<= 1) {
        int t = __shfl_up_sync(0xffffffffu, s, off);
        if (lane >= off) s += t;
    }
    if (lane == 31) wsum[wid] = s;
    __syncthreads();
    if (wid == 0) {
        int t = wsum[lane];
        #pragma unroll
        for (int off = 1; off < 32; off <<= 1) {
            int u = __shfl_up_sync(0xffffffffu, t, off);
            if (lane >= off) t += u;
        }
        wsum[lane] = t;
    }
    __syncthreads();
    int woff = (wid > 0) ? wsum[wid - 1] : 0;
    if (i < NN) g_rowstart[i] = s - v + woff;
    if (tid == 1023) g_bsum[blockIdx.x] = s + woff;
}

__global__ void scanB_kernel(int nblk) {
    __shared__ int tmp[128];
    int t = threadIdx.x;
    tmp[t] = (t < nblk) ? g_bsum[t] : 0;
    __syncthreads();
    if (t == 0) {
        int acc = 0;
        for (int i = 0; i < nblk; i++) { int v = tmp[i]; tmp[i] = acc; acc += v; }
    }
    __syncthreads();
    if (t < nblk) g_bsum[t] = tmp[t];
}

__global__ void __launch_bounds__(1024) scanC_kernel() {
    int i = blockIdx.x * 1024 + threadIdx.x;
    if (i < NN) {
        int rs = g_rowstart[i] + g_bsum[blockIdx.x];
        g_rowstart[i] = rs;
        g_cursor[i]   = rs;
        g_dinv[i]     = rsqrtf(g_deg[i]);
    }
}

// ---------------------------------------------------------------------------
__global__ void pad_kernel() {
    int i = blockIdx.x * blockDim.x + threadIdx.x;
    if (i >= NN) return;
    int cnt  = g_cnt[i];
    int cntp = (cnt + 3) & ~3;
    int rs   = g_rowstart[i];
    for (int k = cnt; k < cntp; k++) g_edges[rs + k] = 0ull;
}

// ---------------------------------------------------------------------------
__global__ void scatter_kernel(const void* __restrict__ ei,
                               const float* __restrict__ ew) {
    int e = blockIdx.x * blockDim.x + threadIdx.x;
    if (e >= NE) return;
    int   r = edge_idx(ei, e);
    int   c = edge_idx(ei, (size_t)NE + e);
    float nw = g_dinv[r] * __ldg(&ew[e]) * g_dinv[c];
    int pos = atomicAdd(&g_cursor[c], 1);
    g_edges[pos] = (unsigned long long)(unsigned)r |
                   ((unsigned long long)__float_as_uint(nw) << 32);
}

// ---------------------------------------------------------------------------
// U = x @ Vc (raw), f32x2 dual-FMA, fp16 output.
// ---------------------------------------------------------------------------
__global__ void __launch_bounds__(256) gemm_u_kernel(const float* __restrict__ x) {
    __shared__ float xs[32][66];
    __shared__ float vs[32][96];
    int tid = threadIdx.x;
    int rg = tid >> 5, cj = tid & 31;
    int m0 = blockIdx.x * 64;

    unsigned long long acc[4][3];
    #pragma unroll
    for (int p = 0; p < 4; p++)
        #pragma unroll
        for (int t = 0; t < 3; t++) acc[p][t] = 0ull;

    for (int kb = 0; kb < FIN; kb += 32) {
        #pragma unroll
        for (int i = 0; i < 2; i++) {
            int s = tid + i * 256;
            int nd = s >> 3, k4 = s & 7;
            int gn = m0 + nd; if (gn >= NN) gn = NN - 1;
            float4 v = *(const float4*)&x[(size_t)gn * FIN + kb + k4 * 4];
            xs[k4 * 4 + 0][nd] = v.x;
            xs[k4 * 4 + 1][nd] = v.y;
            xs[k4 * 4 + 2][nd] = v.z;
            xs[k4 * 4 + 3][nd] = v.w;
        }
        #pragma unroll
        for (int i = 0; i < 12; i++) {
            int idx = tid + i * 256;
            int kk = idx / 96, j = idx - kk * 96;
            vs[kk][j] = g_Vc[(kb + kk) * G3 + j];
        }
        __syncthreads();
        #pragma unroll
        for (int kk = 0; kk < 32; kk++) {
            unsigned long long xp[4];
            #pragma unroll
            for (int p = 0; p < 4; p++)
                xp[p] = *(const unsigned long long*)&xs[kk][rg * 8 + p * 2];
            float b0 = vs[kk][cj], b1 = vs[kk][cj + 32], b2 = vs[kk][cj + 64];
            unsigned long long bb0 = packff(b0, b0);
            unsigned long long bb1 = packff(b1, b1);
            unsigned long long bb2 = packff(b2, b2);
            #pragma unroll
            for (int p = 0; p < 4; p++) {
                ffma2(acc[p][0], xp[p], bb0);
                ffma2(acc[p][1], xp[p], bb1);
                ffma2(acc[p][2], xp[p], bb2);
            }
        }
        __syncthreads();
    }
    #pragma unroll
    for (int p = 0; p < 4; p++) {
        int n0 = m0 + rg * 8 + p * 2;
        if (n0 >= NN) continue;
        bool ok1 = (n0 + 1 < NN);
        #pragma unroll
        for (int t = 0; t < 3; t++) {
            union { unsigned long long u; float2 f; } cv; cv.u = acc[p][t];
            g_U[(size_t)n0 * G3 + cj + t * 32] = __float2half(cv.f.x);
            if (ok1) g_U[(size_t)(n0 + 1) * G3 + cj + t * 32] = __float2half(cv.f.y);
        }
    }
}

// ---------------------------------------------------------------------------
// 4-edge gather body (12 independent fp16 loads in flight)
// ---------------------------------------------------------------------------
#define EDGE4(T)                                                               \
    {                                                                          \
        unsigned long long p0 = __shfl_sync(0xffffffffu, pk, (T));             \
        unsigned long long p1 = __shfl_sync(0xffffffffu, pk, (T) + 1);         \
        unsigned long long p2 = __shfl_sync(0xffffffffu, pk, (T) + 2);         \
        unsigned long long p3 = __shfl_sync(0xffffffffu, pk, (T) + 3);         \
        const __half* u0 = g_U + (size_t)(unsigned)p0 * G3;                    \
        const __half* u1 = g_U + (size_t)(unsigned)p1 * G3;                    \
        const __half* u2 = g_U + (size_t)(unsigned)p2 * G3;                    \
        const __half* u3 = g_U + (size_t)(unsigned)p3 * G3;                    \
        __half h00 = __ldg(u0 + lane), h01 = __ldg(u0 + lane + 32), h02 = __ldg(u0 + lane + 64); \
        __half h10 = __ldg(u1 + lane), h11 = __ldg(u1 + lane + 32), h12 = __ldg(u1 + lane + 64); \
        __half h20 = __ldg(u2 + lane), h21 = __ldg(u2 + lane + 32), h22 = __ldg(u2 + lane + 64); \
        __half h30 = __ldg(u3 + lane), h31 = __ldg(u3 + lane + 32), h32 = __ldg(u3 + lane + 64); \
        float w0 = __uint_as_float((unsigned)(p0 >> 32));                      \
        float w1 = __uint_as_float((unsigned)(p1 >> 32));                      \
        float w2 = __uint_as_float((unsigned)(p2 >> 32));                      \
        float w3 = __uint_as_float((unsigned)(p3 >> 32));                      \
        a0 = fmaf(w0, __half2float(h00), a0); a1 = fmaf(w0, __half2float(h01), a1); a2 = fmaf(w0, __half2float(h02), a2); \
        a0 = fmaf(w1, __half2float(h10), a0); a1 = fmaf(w1, __half2float(h11), a1); a2 = fmaf(w1, __half2float(h12), a2); \
        a0 = fmaf(w2, __half2float(h20), a0); a1 = fmaf(w2, __half2float(h21), a1); a2 = fmaf(w2, __half2float(h22), a2); \
        a0 = fmaf(w3, __half2float(h30), a0); a1 = fmaf(w3, __half2float(h31), a1); a2 = fmaf(w3, __half2float(h32), a2); \
    }

// ---------------------------------------------------------------------------
// fused gather + gates + head. Warp per node; padded CSR.
// ---------------------------------------------------------------------------
__global__ void __launch_bounds__(256) gather_gates_kernel(
    const float* __restrict__ hprev,
    const float* __restrict__ whead,
    const float* __restrict__ bhead,
    float* __restrict__ out)
{
    __shared__ float Ws[3 * HID * HID];
    __shared__ float csts[G3];
    int tid = threadIdx.x;
    for (int i = tid; i < 3 * HID * HID; i += 256) Ws[i] = g_Wt[i];
    if (tid < G3) csts[tid] = g_cst[tid];
    __syncthreads();

    int warp = tid >> 5, lane = tid & 31;
    int n = blockIdx.x * 8 + warp;       // grid = 12500 -> exactly N nodes

    float dc = __ldg(&g_dinv[n]);
    float sl = dc * dc;                  // self-loop norm
    const __half* un = g_U + (size_t)n * G3;
    float a0 = sl * __half2float(__ldg(un + lane));
    float a1 = sl * __half2float(__ldg(un + lane + 32));
    float a2 = sl * __half2float(__ldg(un + lane + 64));

    int start = __ldg(&g_rowstart[n]);
    int cntp  = (__ldg(&g_cnt[n]) + 3) & ~3;
    const unsigned long long* el = g_edges + start;

    for (int b = 0; b < cntp; b += 32) {
        int m = min(32, cntp - b);       // multiple of 4
        unsigned long long pk = (lane < m) ? __ldg(&el[b + lane]) : 0ull;
        if (m == 32) {
            #pragma unroll
            for (int t = 0; t < 32; t += 4) EDGE4(t)
        } else {
            for (int t = 0; t < m; t += 4) EDGE4(t)
        }
    }

    // gates
    float h  = hprev[(size_t)n * HID + lane];
    float zp = a0 + csts[lane];
    float rp = a1 + csts[lane + 32];
    float hp = a2 + csts[lane + 64];

    const float* Wz = Ws;
    const float* Wr = Ws + HID * HID;
    const float* Wh = Ws + 2 * HID * HID;
    #pragma unroll
    for (int k = 0; k < HID; k++) {
        float hk = __shfl_sync(0xffffffffu, h, k);
        zp += hk * Wz[k * HID + lane];
        rp += hk * Wr[k * HID + lane];
    }
    float Z = 1.f / (1.f + __expf(-zp));
    float R = 1.f / (1.f + __expf(-rp));
    float hr = h * R;
    #pragma unroll
    for (int k = 0; k < HID; k++) {
        float hk = __shfl_sync(0xffffffffu, hr, k);
        hp += hk * Wh[k * HID + lane];
    }
    float Ht = tanhf(hp);
    float Hn = Z * h + (1.f - Z) * Ht;

    out[(size_t)NN + (size_t)n * HID + lane] = Hn;

    float yv = fmaxf(Hn, 0.f) * __ldg(&whead[lane]);
    #pragma unroll
    for (int off = 16; off > 0; off >>= 1)
        yv += __shfl_down_sync(0xffffffffu, yv, off);
    if (lane == 0) out[n] = yv + __ldg(bhead);
}

// ---------------------------------------------------------------------------
extern "C" void kernel_launch(void* const* d_in, const int* in_sizes, int n_in,
                              void* d_out, int out_size) {
    const float* x     = (const float*)d_in[0];
    const void*  ei    = d_in[1];
    const float* ew    = (const float*)d_in[2];
    const float* hprev = (const float*)d_in[3];
    const float* Wc[3], *bc[3], *Wl[3], *bl[3];
    for (int g = 0; g < 3; g++) {
        Wc[g] = (const float*)d_in[4 + g * 4];
        bc[g] = (const float*)d_in[5 + g * 4];
        Wl[g] = (const float*)d_in[6 + g * 4];
        bl[g] = (const float*)d_in[7 + g * 4];
    }
    const float* whead = (const float*)d_in[16];
    const float* bhead = (const float*)d_in[17];
    float* out = (float*)d_out;

    const int nscan = (NN + 1023) / 1024;   // 98
    const int nprep = (FIN * G3 + G3 + 3 * HID * HID + 255) / 256;  // 61

    // side stream + fork/join events (created once; host-side resources only)
    static cudaStream_t sB = nullptr;
    static cudaEvent_t  evF = nullptr, evJ = nullptr;
    if (sB == nullptr) {
        cudaStreamCreateWithFlags(&sB, cudaStreamNonBlocking);
        cudaEventCreateWithFlags(&evF, cudaEventDisableTiming);
        cudaEventCreateWithFlags(&evJ, cudaEventDisableTiming);
    }

    // stream 0: detect + init
    detect_kernel<<<1, 256>>>((const int*)ei);
    init_kernel<<<(NN + 255) / 256, 256>>>();

    // fork: B chain (prep -> gemm) on side stream, independent of edge chain
    cudaEventRecord(evF, 0);
    cudaStreamWaitEvent(sB, evF, 0);
    prep_kernel<<<nprep, 256, 0, sB>>>(Wc[0], bc[0], Wl[0], bl[0],
                                       Wc[1], bc[1], Wl[1], bl[1],
                                       Wc[2], bc[2], Wl[2], bl[2]);
    gemm_u_kernel<<<(NN + 63) / 64, 256, 0, sB>>>(x);

    // C chain on stream 0: count -> scan -> pad -> scatter
    count_kernel<<<(NE + 255) / 256, 256>>>(ei, ew);
    scanA_kernel<<<nscan, 1024>>>();
    scanB_kernel<<<1, 128>>>(nscan);
    scanC_kernel<<<nscan, 1024>>>();
    pad_kernel<<<(NN + 255) / 256, 256>>>();
    scatter_kernel<<<(NE + 255) / 256, 256>>>(ei, ew);

    // join B into 0, then gather
    cudaEventRecord(evJ, sB);
    cudaStreamWaitEvent(0, evJ, 0);
    gather_gates_kernel<<<NN / 8, 256>>>(hprev, whead, bhead, out);
}